// round 1
// baseline (speedup 1.0000x reference)
#include <cuda_runtime.h>

// Correlation1D: out[b,d,h,w] = (1/C) * sum_c in1[b,c,h,w] * in2[b,c,h,w+d-40]
// B=8, C=256, H=96, W=192, D=81 (disp -40..40)

#define BB 8
#define CC_TOT 256
#define HH 96
#define WW 192
#define DD 81
#define PADC 40
#define HW (HH*WW)          // 18432
#define CHW (CC_TOT*HW)

#define WT 64               // w-tile per block
#define CCH 16              // C chunk staged in smem
#define TD 6                // disps per thread (16 d-groups * 6 = 96 computed, 81 stored)
#define S2W 160             // smem width for in2 tile: cols w0-40 .. w0+118

__global__ __launch_bounds__(256)
void corr1d_kernel(const float* __restrict__ in1,
                   const float* __restrict__ in2,
                   float* __restrict__ out) {
    __shared__ float s1[CCH][WT];
    __shared__ float s2[CCH][S2W];

    const int w0 = blockIdx.x * WT;
    const int h  = blockIdx.y;
    const int b  = blockIdx.z;

    const int tid = threadIdx.x;
    const int dg  = tid & 15;   // lane-contiguous: d-group (b-loads conflict-spread)
    const int wg  = tid >> 4;   // w-group (a-loads broadcast across 16 lanes)

    const float* p1 = in1 + (size_t)b * CHW + (size_t)h * WW + w0;
    const float* p2 = in2 + (size_t)b * CHW + (size_t)h * WW;

    float acc[TD][4];
#pragma unroll
    for (int i = 0; i < TD; i++)
#pragma unroll
        for (int j = 0; j < 4; j++) acc[i][j] = 0.f;

    for (int c0 = 0; c0 < CC_TOT; c0 += CCH) {
        __syncthreads();
        // ---- stage in1 chunk: 16 rows x 64 cols, one float4 per thread ----
        {
            const int row = tid >> 4;   // 0..15
            const int v   = tid & 15;   // float4 index 0..15
            const float4* src = reinterpret_cast<const float4*>(p1 + (size_t)(c0 + row) * HW) + v;
            reinterpret_cast<float4*>(&s1[row][0])[v] = *src;
        }
        // ---- stage in2 chunk: 16 rows x 160 cols, zero-padded OOB ----
        for (int k = tid; k < CCH * S2W; k += 256) {
            const int row = k / S2W;
            const int i   = k - row * S2W;
            const int col = w0 - PADC + i;
            float val = 0.f;
            if (col >= 0 && col < WW) val = p2[(size_t)(c0 + row) * HW + col];
            s2[row][i] = val;
        }
        __syncthreads();

        // ---- accumulate ----
#pragma unroll
        for (int cc = 0; cc < CCH; cc++) {
            float4 av = reinterpret_cast<const float4*>(&s1[cc][0])[wg];
            const float a0 = av.x, a1 = av.y, a2 = av.z, a3 = av.w;
            float bb[4 + TD - 1];
            const int bbase = wg * 4 + dg * TD;   // smem-col of (w, d) pair; max 150+8=158
#pragma unroll
            for (int j = 0; j < 4 + TD - 1; j++) bb[j] = s2[cc][bbase + j];
#pragma unroll
            for (int jd = 0; jd < TD; jd++) {
                acc[jd][0] += a0 * bb[jd + 0];
                acc[jd][1] += a1 * bb[jd + 1];
                acc[jd][2] += a2 * bb[jd + 2];
                acc[jd][3] += a3 * bb[jd + 3];
            }
        }
    }

    // ---- epilogue: scale by 1/C, store d < 81 ----
    const float scale = 1.0f / (float)CC_TOT;
    float* po = out + (size_t)b * DD * HW + (size_t)h * WW + w0 + wg * 4;
#pragma unroll
    for (int jd = 0; jd < TD; jd++) {
        const int d = dg * TD + jd;
        if (d < DD) {
            float4 v = make_float4(acc[jd][0] * scale, acc[jd][1] * scale,
                                   acc[jd][2] * scale, acc[jd][3] * scale);
            *reinterpret_cast<float4*>(po + (size_t)d * HW) = v;
        }
    }
}

extern "C" void kernel_launch(void* const* d_in, const int* in_sizes, int n_in,
                              void* d_out, int out_size) {
    const float* in1 = (const float*)d_in[0];
    const float* in2 = (const float*)d_in[1];
    float* out = (float*)d_out;

    dim3 grid(WW / WT, HH, BB);   // (3, 96, 8)
    corr1d_kernel<<<grid, 256>>>(in1, in2, out);
}

// round 3
// speedup vs baseline: 1.0917x; 1.0917x over previous
#include <cuda_runtime.h>
#include <cstdint>

// Correlation1D via warp-level tf32 mma.sync band-GEMM.
// out[b,d,h,w] = (1/256) * sum_c in1[b,c,h,w] * in2[b,c,h,w+d-40], d in [0,81)
// Per CTA (b,h): D[w, sj] = sum_c in1[c,w] * in2[c, sj-40], w in [0,192), sj = w+d.
// 6 warps, each owns w-range [32*wid, 32*wid+32) and sj-window [m0, m0+112).

#define BB 8
#define CC 256
#define HH 96
#define WW 192
#define DD 81
#define HW (HH*WW)
#define CHW ((size_t)CC*(size_t)HW)

#define KC 16               // k-chunk (c) staged per iteration
#define NKC (CC/KC)         // 16 chunks
#define SAW 200             // sA row stride (conflict-free: 200%32=8)
#define SBW 280             // sB row stride (conflict-free: 280%32=24)
#define SB_OFF (KC*SAW)     // 3200
#define SMEM_WORDS (KC*SAW + KC*SBW)   // 7680 words = 30720 B

__device__ __forceinline__ uint32_t f2tf32(float f) {
    uint32_t u;
    asm("cvt.rna.tf32.f32 %0, %1;" : "=r"(u) : "f"(f));
    return u;
}

__device__ __forceinline__ void mma_tf32(float (&d)[4], const uint32_t (&a)[4],
                                         uint32_t b0, uint32_t b1) {
    asm volatile(
        "mma.sync.aligned.m16n8k8.row.col.f32.tf32.tf32.f32 "
        "{%0,%1,%2,%3}, {%4,%5,%6,%7}, {%8,%9}, {%0,%1,%2,%3};"
        : "+f"(d[0]), "+f"(d[1]), "+f"(d[2]), "+f"(d[3])
        : "r"(a[0]), "r"(a[1]), "r"(a[2]), "r"(a[3]), "r"(b0), "r"(b1));
}

__global__ __launch_bounds__(192, 2)
void corr_hmma(const float* __restrict__ in1, const float* __restrict__ in2,
               float* __restrict__ out) {
    __shared__ uint32_t smem[SMEM_WORDS];

    const int h   = blockIdx.x;
    const int b   = blockIdx.y;
    const int tid = threadIdx.x;
    const int wid = tid >> 5;
    const int lane = tid & 31;
    const int g   = lane >> 2;   // groupID
    const int l4  = lane & 3;    // threadID_in_group
    const int m0  = wid * 32;    // warp's w base

    const float* p1 = in1 + (size_t)b * CHW + (size_t)h * WW;
    const float* p2 = in2 + (size_t)b * CHW + (size_t)h * WW;
    float* pout = out + (size_t)b * DD * HW + (size_t)h * WW;

    float acc[2][12][4];
#pragma unroll
    for (int mt = 0; mt < 2; mt++)
#pragma unroll
        for (int nt = 0; nt < 12; nt++)
#pragma unroll
            for (int ci = 0; ci < 4; ci++) acc[mt][nt][ci] = 0.f;

    for (int kc = 0; kc < NKC; kc++) {
        __syncthreads();
        // ---- stage A chunk: KC rows x 192 w, tf32, float4-vectorized ----
#pragma unroll
        for (int i = tid; i < KC * 48; i += 192) {
            const int row = i / 48;
            const int v   = i - row * 48;
            float4 x = *reinterpret_cast<const float4*>(p1 + (size_t)(kc * KC + row) * HW + v * 4);
            uint4 y;
            y.x = f2tf32(x.x); y.y = f2tf32(x.y); y.z = f2tf32(x.z); y.w = f2tf32(x.w);
            *reinterpret_cast<uint4*>(&smem[row * SAW + v * 4]) = y;
        }
        // ---- stage B chunk: KC rows x 272 cols (sj = j+40, zero-padded OOB) ----
        for (int i = tid; i < KC * 272; i += 192) {
            const int row = i / 272;
            const int sj  = i - row * 272;
            const int jg  = sj - 40;
            float v = 0.f;
            if (jg >= 0 && jg < WW) v = p2[(size_t)(kc * KC + row) * HW + jg];
            smem[SB_OFF + row * SBW + sj] = f2tf32(v);
        }
        __syncthreads();

        // ---- compute: 2 k8 steps per chunk ----
#pragma unroll
        for (int ks = 0; ks < KC; ks += 8) {
            uint32_t a[2][4];
#pragma unroll
            for (int mt = 0; mt < 2; mt++) {
                const int col = m0 + 16 * mt + g;
                a[mt][0] = smem[(ks + l4) * SAW + col];
                a[mt][1] = smem[(ks + l4) * SAW + col + 8];
                a[mt][2] = smem[(ks + l4 + 4) * SAW + col];
                a[mt][3] = smem[(ks + l4 + 4) * SAW + col + 8];
            }
#pragma unroll
            for (int nt = 0; nt < 14; nt++) {
                const int bc = m0 + 8 * nt + g;
                const uint32_t b0 = smem[SB_OFF + (ks + l4) * SBW + bc];
                const uint32_t b1 = smem[SB_OFF + (ks + l4 + 4) * SBW + bc];
                if (nt < 12) mma_tf32(acc[0][nt], a[0], b0, b1);
                if (nt >= 2) mma_tf32(acc[1][nt - 2], a[1], b0, b1);
            }
        }
    }

    // ---- epilogue: diagonal extract d = sj - w, coalesced stores via smem ----
    float* buf = reinterpret_cast<float*>(smem);   // [32][SAW]
#pragma unroll
    for (int chunk = 0; chunk < 3; chunk++) {
        const int d0 = chunk * 32;
        __syncthreads();
#pragma unroll
        for (int mt = 0; mt < 2; mt++) {
#pragma unroll
            for (int nt = 0; nt < 12; nt++) {
                const int ntt = nt + 2 * mt;
#pragma unroll
                for (int ci = 0; ci < 4; ci++) {
                    const int wp = m0 + 16 * mt + g + ((ci & 2) ? 8 : 0);
                    const int sj = m0 + 8 * ntt + 2 * l4 + (ci & 1);
                    const int d  = sj - wp;
                    if (d >= d0 && d < d0 + 32 && d < DD)
                        buf[(d - d0) * SAW + wp] = acc[mt][nt][ci] * (1.0f / 256.0f);
                }
            }
        }
        __syncthreads();
        const int dmax = (DD - d0 < 32) ? (DD - d0) : 32;
        for (int i = tid; i < dmax * 48; i += 192) {
            const int dd = i / 48;
            const int v  = i - dd * 48;
            float4 val = *reinterpret_cast<float4*>(&buf[dd * SAW + v * 4]);
            *reinterpret_cast<float4*>(pout + (size_t)(d0 + dd) * HW + v * 4) = val;
        }
    }
}

extern "C" void kernel_launch(void* const* d_in, const int* in_sizes, int n_in,
                              void* d_out, int out_size) {
    const float* in1 = (const float*)d_in[0];
    const float* in2 = (const float*)d_in[1];
    float* out = (float*)d_out;

    dim3 grid(HH, BB);   // 768 CTAs
    corr_hmma<<<grid, 192>>>(in1, in2, out);
}

// round 4
// speedup vs baseline: 2.2967x; 2.1039x over previous
#include <cuda_runtime.h>
#include <cstdint>

// Correlation1D via warp-level tf32 mma.sync band-GEMM, register-double-buffered.
// out[b,d,h,w] = (1/256) * sum_c in1[b,c,h,w] * in2[b,c,h,w+d-40], d in [0,81)
// Per CTA (b,h): D[w, sj] = sum_c in1[c,w] * in2[c, sj-40], w in [0,192), sj = w+d in [0,272).
// 24 warps: warp (mt, half): m-tile w0=16*mt, n-tiles ntg = half*7 + {0..6}, ntg<13.

#define BB 8
#define CC 256
#define HH 96
#define WW 192
#define DD 81
#define HW (HH*WW)
#define CHW ((size_t)CC*(size_t)HW)

#define NTHR 768
#define KC 16               // k-rows per chunk
#define NKC (CC/KC)         // 16 chunks
#define SAW 200             // A row stride (words), 200%32=8 -> conflict-free frags
#define SBW 280             // B row stride (words), 280%32=24 -> conflict-free frags
#define SB_OFF (KC*SAW)     // 3200
#define SMEM_WORDS (KC*SAW + KC*SBW)   // 7680 words = 30 KB

__device__ __forceinline__ uint32_t f2tf32(float f) {
    uint32_t u;
    asm("cvt.rna.tf32.f32 %0, %1;" : "=r"(u) : "f"(f));
    return u;
}

__device__ __forceinline__ void mma_tf32(float (&d)[4], const uint32_t (&a)[4],
                                         uint32_t b0, uint32_t b1) {
    asm volatile(
        "mma.sync.aligned.m16n8k8.row.col.f32.tf32.tf32.f32 "
        "{%0,%1,%2,%3}, {%4,%5,%6,%7}, {%8,%9}, {%0,%1,%2,%3};"
        : "+f"(d[0]), "+f"(d[1]), "+f"(d[2]), "+f"(d[3])
        : "r"(a[0]), "r"(a[1]), "r"(a[2]), "r"(a[3]), "r"(b0), "r"(b1));
}

__global__ __launch_bounds__(NTHR, 1)
void corr_hmma2(const float* __restrict__ in1, const float* __restrict__ in2,
                float* __restrict__ out) {
    __shared__ uint32_t smem[SMEM_WORDS];

    const int h    = blockIdx.x;
    const int b    = blockIdx.y;
    const int tid  = threadIdx.x;
    const int wid  = tid >> 5;
    const int lane = tid & 31;
    const int g    = lane >> 2;
    const int l4   = lane & 3;
    const int mt   = wid >> 1;       // 0..11
    const int half = wid & 1;        // 0: ntg 0..6, 1: ntg 7..12
    const int w0   = mt * 16;

    const float* p1 = in1 + (size_t)b * CHW + (size_t)h * WW;
    const float* p2 = in2 + (size_t)b * CHW + (size_t)h * WW;
    float* pout = out + (size_t)b * DD * HW + (size_t)h * WW;

    // staging indices (fixed per thread)
    const int arow = tid / 48, av = tid - arow * 48;        // A: 16 x 48 float4
    const int b0row = tid / 68, b0q = tid - b0row * 68;     // B slot 0: idx = tid (< 1088)
    const int i1 = tid + NTHR;                              // B slot 1: idx = tid+768
    const int b1row = i1 / 68, b1q = i1 - b1row * 68;
    const bool hasB1 = (i1 < KC * 68);                      // tid < 320

    float acc[7][4];
#pragma unroll
    for (int nt = 0; nt < 7; nt++)
#pragma unroll
        for (int ci = 0; ci < 4; ci++) acc[nt][ci] = 0.f;

    float4 ra, rb0, rb1;
    // ---- prologue: load chunk 0 into registers ----
    {
        ra = *reinterpret_cast<const float4*>(p1 + (size_t)arow * HW + av * 4);
        const int jg0 = b0q * 4 - 40;
        rb0 = (jg0 >= 0 && jg0 < WW)
            ? *reinterpret_cast<const float4*>(p2 + (size_t)b0row * HW + jg0)
            : make_float4(0.f, 0.f, 0.f, 0.f);
        rb1 = make_float4(0.f, 0.f, 0.f, 0.f);
        if (hasB1) {
            const int jg1 = b1q * 4 - 40;
            if (jg1 >= 0 && jg1 < WW)
                rb1 = *reinterpret_cast<const float4*>(p2 + (size_t)b1row * HW + jg1);
        }
    }

    for (int kc = 0; kc < NKC; kc++) {
        // ---- cvt + STS current chunk ----
        {
            uint4 ya;
            ya.x = f2tf32(ra.x); ya.y = f2tf32(ra.y); ya.z = f2tf32(ra.z); ya.w = f2tf32(ra.w);
            *reinterpret_cast<uint4*>(&smem[arow * SAW + av * 4]) = ya;
            uint4 yb;
            yb.x = f2tf32(rb0.x); yb.y = f2tf32(rb0.y); yb.z = f2tf32(rb0.z); yb.w = f2tf32(rb0.w);
            *reinterpret_cast<uint4*>(&smem[SB_OFF + b0row * SBW + b0q * 4]) = yb;
            if (hasB1) {
                uint4 yc;
                yc.x = f2tf32(rb1.x); yc.y = f2tf32(rb1.y); yc.z = f2tf32(rb1.z); yc.w = f2tf32(rb1.w);
                *reinterpret_cast<uint4*>(&smem[SB_OFF + b1row * SBW + b1q * 4]) = yc;
            }
        }
        __syncthreads();

        // ---- prefetch next chunk into registers (latency hidden by compute) ----
        if (kc + 1 < NKC) {
            const size_t ko = (size_t)(kc + 1) * KC * HW;
            ra = *reinterpret_cast<const float4*>(p1 + ko + (size_t)arow * HW + av * 4);
            const int jg0 = b0q * 4 - 40;
            rb0 = (jg0 >= 0 && jg0 < WW)
                ? *reinterpret_cast<const float4*>(p2 + ko + (size_t)b0row * HW + jg0)
                : make_float4(0.f, 0.f, 0.f, 0.f);
            if (hasB1) {
                const int jg1 = b1q * 4 - 40;
                rb1 = (jg1 >= 0 && jg1 < WW)
                    ? *reinterpret_cast<const float4*>(p2 + ko + (size_t)b1row * HW + jg1)
                    : make_float4(0.f, 0.f, 0.f, 0.f);
            }
        }

        // ---- compute: 2 k8 steps on current chunk ----
#pragma unroll
        for (int ks = 0; ks < KC; ks += 8) {
            uint32_t a[4];
            a[0] = smem[(ks + l4) * SAW + w0 + g];
            a[1] = smem[(ks + l4) * SAW + w0 + g + 8];
            a[2] = smem[(ks + l4 + 4) * SAW + w0 + g];
            a[3] = smem[(ks + l4 + 4) * SAW + w0 + g + 8];
#pragma unroll
            for (int nt = 0; nt < 7; nt++) {
                const int ntg = half * 7 + nt;
                if (ntg < 13) {
                    const int bc = w0 + 8 * ntg + g;
                    const uint32_t bb0 = smem[SB_OFF + (ks + l4) * SBW + bc];
                    const uint32_t bb1 = smem[SB_OFF + (ks + l4 + 4) * SBW + bc];
                    mma_tf32(acc[nt], a, bb0, bb1);
                }
            }
        }
        __syncthreads();
    }

    // ---- epilogue: diagonal extract d = sj - wp, coalesced stores via smem ----
    float* buf = reinterpret_cast<float*>(smem);   // [32][SAW] floats
#pragma unroll
    for (int chunk = 0; chunk < 3; chunk++) {
        const int d0 = chunk * 32;
        if (chunk) __syncthreads();   // prior chunk's stores done before overwrite
#pragma unroll
        for (int nt = 0; nt < 7; nt++) {
            const int ntg = half * 7 + nt;
            if (ntg < 13) {
#pragma unroll
                for (int ci = 0; ci < 4; ci++) {
                    const int wp = w0 + g + ((ci & 2) ? 8 : 0);
                    const int sj = w0 + 8 * ntg + 2 * l4 + (ci & 1);
                    const int d  = sj - wp;
                    if (d >= d0 && d < d0 + 32 && d < DD)
                        buf[(d - d0) * SAW + wp] = acc[nt][ci] * (1.0f / 256.0f);
                }
            }
        }
        __syncthreads();
        const int dmax = (DD - d0 < 32) ? (DD - d0) : 32;
        for (int i = tid; i < dmax * 48; i += NTHR) {
            const int dd = i / 48;
            const int v  = i - dd * 48;
            *reinterpret_cast<float4*>(pout + (size_t)(d0 + dd) * HW + v * 4) =
                *reinterpret_cast<float4*>(&buf[dd * SAW + v * 4]);
        }
    }
}

extern "C" void kernel_launch(void* const* d_in, const int* in_sizes, int n_in,
                              void* d_out, int out_size) {
    const float* in1 = (const float*)d_in[0];
    const float* in2 = (const float*)d_in[1];
    float* out = (float*)d_out;

    dim3 grid(HH, BB);   // 768 CTAs x 768 threads
    corr_hmma2<<<grid, NTHR>>>(in1, in2, out);
}

// round 7
// speedup vs baseline: 3.1273x; 1.3617x over previous
#include <cuda_runtime.h>
#include <cstdint>

// Correlation1D via warp-level tf32 mma.sync band-GEMM, cp.async double-buffered.
// out[b,d,h,w] = (1/256) * sum_c in1[b,c,h,w] * in2[b,c,h,w+d-40], d in [0,81)
// Per CTA (b,h): D[w, sj] = sum_c in1[c,w] * in2[c, sj-40], sj = w+d in [0,272).
// 12 warps: warp mt owns w0=16*mt, n-tiles sj in [w0, w0+96) -> 12 tiles of 8.
// f32 staged raw via cp.async (zero-fill OOB); RNA->tf32 applied to fragments after LDS.
// NOTE: an empty cp.async group is committed on tail iterations so that
// wait_group 1 always proves chunk kc is complete (R6 raced on the last chunk).

#define BB 8
#define CC 256
#define HH 96
#define WW 192
#define DD 81
#define HW (HH*WW)
#define CHW ((size_t)CC*(size_t)HW)

#define NTHR 384
#define KC 16                 // k-rows per chunk
#define NKC (CC/KC)           // 16 chunks
#define SAW 200               // A row stride (words): conflict-free
#define SBW 280               // B row stride (words): conflict-free
#define SB_OFF (KC*SAW)       // 3200 words
#define STG_W (KC*SAW + KC*SBW)   // 7680 words per stage
#define SMEM_BYTES (2*STG_W*4)    // 61440

__device__ __forceinline__ void cp16(uint32_t daddr, const float* src, uint32_t sz) {
    asm volatile("cp.async.cg.shared.global [%0], [%1], 16, %2;"
                 :: "r"(daddr), "l"(src), "r"(sz));
}

__device__ __forceinline__ uint32_t f2tf32(uint32_t raw) {
    uint32_t u;
    asm("cvt.rna.tf32.f32 %0, %1;" : "=r"(u) : "f"(__uint_as_float(raw)));
    return u;
}

__device__ __forceinline__ void mma_tf32(float (&d)[4], const uint32_t (&a)[4],
                                         uint32_t b0, uint32_t b1) {
    asm volatile(
        "mma.sync.aligned.m16n8k8.row.col.f32.tf32.tf32.f32 "
        "{%0,%1,%2,%3}, {%4,%5,%6,%7}, {%8,%9}, {%0,%1,%2,%3};"
        : "+f"(d[0]), "+f"(d[1]), "+f"(d[2]), "+f"(d[3])
        : "r"(a[0]), "r"(a[1]), "r"(a[2]), "r"(a[3]), "r"(b0), "r"(b1));
}

extern __shared__ uint32_t smem[];

__global__ __launch_bounds__(NTHR, 2)
void corr_hmma5(const float* __restrict__ in1, const float* __restrict__ in2,
                float* __restrict__ out) {
    const int h    = blockIdx.x;
    const int b    = blockIdx.y;
    const int tid  = threadIdx.x;
    const int wid  = tid >> 5;
    const int lane = tid & 31;
    const int g    = lane >> 2;
    const int l4   = lane & 3;
    const int w0   = wid * 16;

    const float* p1 = in1 + (size_t)b * CHW + (size_t)h * WW;
    const float* p2 = in2 + (size_t)b * CHW + (size_t)h * WW;
    float* pout = out + (size_t)b * DD * HW + (size_t)h * WW;

    uint32_t smem_u32;
    {
        uint32_t a;
        asm("{ .reg .u64 t; cvta.to.shared.u64 t, %1; cvt.u32.u64 %0, t; }"
            : "=r"(a) : "l"((const void*)smem));
        smem_u32 = a;
    }

    // per-thread cp.async assignments (2 A ops + up to 3 B ops per thread)
    const int a0 = tid,        a0r = a0 / 48, a0s = a0 % 48;
    const int a1 = tid + 384,  a1r = a1 / 48, a1s = a1 % 48;
    const int b0i = tid,       b0r = b0i / 68, b0j = b0i % 68;
    const int b1i = tid + 384, b1r = b1i / 68, b1j = b1i % 68;
    const int b2i = tid + 768; const int b2r = b2i / 68, b2j = b2i % 68;
    const bool hasB2 = (b2i < KC * 68);
    const uint32_t b0sz = (b0j >= 10 && b0j < 58) ? 16u : 0u;
    const uint32_t b1sz = (b1j >= 10 && b1j < 58) ? 16u : 0u;
    const uint32_t b2sz = (b2j >= 10 && b2j < 58) ? 16u : 0u;

    float acc[12][4];
#pragma unroll
    for (int nt = 0; nt < 12; nt++)
#pragma unroll
        for (int ci = 0; ci < 4; ci++) acc[nt][ci] = 0.f;

    auto issue = [&](int kc, int st) {
        if (kc < NKC) {
            const uint32_t sb = smem_u32 + (uint32_t)st * STG_W * 4;
            const size_t ko = (size_t)kc * KC * HW;
            cp16(sb + (a0r * SAW + a0s * 4) * 4, p1 + ko + (size_t)a0r * HW + a0s * 4, 16u);
            cp16(sb + (a1r * SAW + a1s * 4) * 4, p1 + ko + (size_t)a1r * HW + a1s * 4, 16u);
            cp16(sb + (SB_OFF + b0r * SBW + b0j * 4) * 4, p2 + ko + (size_t)b0r * HW + b0j * 4 - 40, b0sz);
            cp16(sb + (SB_OFF + b1r * SBW + b1j * 4) * 4, p2 + ko + (size_t)b1r * HW + b1j * 4 - 40, b1sz);
            if (hasB2)
                cp16(sb + (SB_OFF + b2r * SBW + b2j * 4) * 4, p2 + ko + (size_t)b2r * HW + b2j * 4 - 40, b2sz);
        }
        // ALWAYS commit (possibly-empty group) so the wait_group counting
        // invariant holds at the tail iterations.
        asm volatile("cp.async.commit_group;" ::: "memory");
    };

    issue(0, 0);
    issue(1, 1);

    for (int kc = 0; kc < NKC; kc++) {
        asm volatile("cp.async.wait_group 1;" ::: "memory");
        __syncthreads();
        const uint32_t* sb = smem + (kc & 1) * STG_W;

#pragma unroll
        for (int ks = 0; ks < KC; ks += 8) {
            uint32_t a[4];
            a[0] = f2tf32(sb[(ks + l4) * SAW + w0 + g]);
            a[1] = f2tf32(sb[(ks + l4) * SAW + w0 + g + 8]);
            a[2] = f2tf32(sb[(ks + l4 + 4) * SAW + w0 + g]);
            a[3] = f2tf32(sb[(ks + l4 + 4) * SAW + w0 + g + 8]);
#pragma unroll
            for (int nt = 0; nt < 12; nt++) {
                const int bc = w0 + 8 * nt + g;
                const uint32_t bb0 = f2tf32(sb[SB_OFF + (ks + l4) * SBW + bc]);
                const uint32_t bb1 = f2tf32(sb[SB_OFF + (ks + l4 + 4) * SBW + bc]);
                mma_tf32(acc[nt], a, bb0, bb1);
            }
        }
        __syncthreads();   // all reads of this stage done before re-filling it
        issue(kc + 2, kc & 1);
    }

    // ---- epilogue: diagonal extract d = sj - wp, coalesced float4 stores ----
    float* buf = reinterpret_cast<float*>(smem);   // [32][SAW] floats
#pragma unroll
    for (int chunk = 0; chunk < 3; chunk++) {
        const int d0 = chunk * 32;
        if (chunk) __syncthreads();
#pragma unroll
        for (int nt = 0; nt < 12; nt++) {
#pragma unroll
            for (int ci = 0; ci < 4; ci++) {
                const int wp = w0 + g + ((ci & 2) ? 8 : 0);
                const int sj = w0 + 8 * nt + 2 * l4 + (ci & 1);
                const int d  = sj - wp;
                if (d >= d0 && d < d0 + 32 && d < DD)
                    buf[(d - d0) * SAW + wp] = acc[nt][ci] * (1.0f / 256.0f);
            }
        }
        __syncthreads();
        const int dmax = (DD - d0 < 32) ? (DD - d0) : 32;
        for (int i = tid; i < dmax * 48; i += NTHR) {
            const int dd = i / 48;
            const int v  = i - dd * 48;
            *reinterpret_cast<float4*>(pout + (size_t)(d0 + dd) * HW + v * 4) =
                *reinterpret_cast<float4*>(&buf[dd * SAW + v * 4]);
        }
    }
}

extern "C" void kernel_launch(void* const* d_in, const int* in_sizes, int n_in,
                              void* d_out, int out_size) {
    const float* in1 = (const float*)d_in[0];
    const float* in2 = (const float*)d_in[1];
    float* out = (float*)d_out;

    cudaFuncSetAttribute(corr_hmma5, cudaFuncAttributeMaxDynamicSharedMemorySize, SMEM_BYTES);
    dim3 grid(HH, BB);   // 768 CTAs x 384 threads
    corr_hmma5<<<grid, NTHR, SMEM_BYTES>>>(in1, in2, out);
}